// round 17
// baseline (speedup 1.0000x reference)
#include <cuda_runtime.h>
#include <cuda_bf16.h>

// VoxelCollisionCost: B=1024, H=32, L=8 links, S=8 spheres, 256^3 SDF grid.
// ILP=4: each thread processes FOUR (b,h) units -> 32 gathers in flight per
// warp (under the ~55/warp outstanding-LDG cap). 128-thread blocks keep the
// grid at 512 (same per-SM residency as the ILP=2 winner) while halving the
// number of latency-waits per unit of work.

#define GRID_N   256
#define N_LINKS  8
#define N_SPH    8
#define BH_PER_BLOCK 64   // 16 bh-lane-groups x 4 units
#define ILP 4

__global__ void __launch_bounds__(128) vox_cost_kernel(
    const float* __restrict__ link_pos,   // [B,H,8,3]
    const float* __restrict__ link_rot,   // [B,H,8,3,3]
    const float* __restrict__ sph_ctr,    // [8,8,3]
    const float* __restrict__ sph_rad,    // [8,8]
    const float* __restrict__ sdf,        // [256,256,256]
    const float* __restrict__ weight,     // [1]
    float* __restrict__ out)              // [B,H]
{
    // Packed model [l][9] float4, slot s = {cx,cy,cz,r}; stride 9 -> LDS.128
    // conflict-free, and .w re-reads broadcast.
    __shared__ float4 s_model[N_LINKS * 9];
    // 64 bh-groups: pos 1536 floats + rot 4608 floats
    __shared__ float s_stage[6144];

    const int tid = threadIdx.x;

    // ---- stage poses: 12 float4 per thread, fully coalesced ----
    const float4* posv = reinterpret_cast<const float4*>(link_pos) + (size_t)blockIdx.x * 384;
    const float4* rotv = reinterpret_cast<const float4*>(link_rot) + (size_t)blockIdx.x * 1152;
    float4* s4 = reinterpret_cast<float4*>(s_stage);
    #pragma unroll
    for (int k = 0; k < 12; k++) {
        const int j = tid + k * 128;
        s4[j] = (j < 384) ? __ldg(posv + j) : __ldg(rotv + (j - 384));
    }

    // ---- model repack (overlaps with staging loads) ----
    if (tid < 64) {
        const int pl = tid >> 3, ps = tid & 7;
        float4 m;
        m.x = __ldg(sph_ctr + 3 * tid + 0);
        m.y = __ldg(sph_ctr + 3 * tid + 1);
        m.z = __ldg(sph_ctr + 3 * tid + 2);
        m.w = __ldg(sph_rad + tid);
        s_model[pl * 9 + ps] = m;
    }
    __syncthreads();

    const int lbh = tid >> 3;      // unit-u bh: lbh + u*16  (lbh 0..15)
    const int l   = tid & 7;       // link index
    const float* S = s_stage;

    // ---- 4 units: per unit, compute indices and ISSUE gathers immediately;
    //      lin dies fast, gather results accumulate (32 loads in flight). ----
    float g[ILP][N_SPH];
    #pragma unroll
    for (int u = 0; u < ILP; u++) {
        const int bh = lbh + u * 16;
        const float* R = S + 1536 + bh * 72 + l * 9;
        const float* P = S +        bh * 24 + l * 3;
        const float r00 = R[0], r01 = R[1], r02 = R[2];
        const float r10 = R[3], r11 = R[4], r12 = R[5];
        const float r20 = R[6], r21 = R[7], r22 = R[8];
        const float px = P[0], py = P[1], pz = P[2];
        #pragma unroll
        for (int s = 0; s < N_SPH; s++) {
            const float4 m = s_model[l * 9 + s];
            const float x = fmaf(r00, m.x, fmaf(r01, m.y, fmaf(r02, m.z, px)));
            const float y = fmaf(r10, m.x, fmaf(r11, m.y, fmaf(r12, m.z, py)));
            const float z = fmaf(r20, m.x, fmaf(r21, m.y, fmaf(r22, m.z, pz)));
            // exact reference semantics: floor((p + 1.28)/0.01), rn-division
            int ix = (int)floorf(__fdiv_rn(x + 1.28f, 0.01f));
            int iy = (int)floorf(__fdiv_rn(y + 1.28f, 0.01f));
            int iz = (int)floorf(__fdiv_rn(z + 1.28f, 0.01f));
            ix = min(max(ix, 0), GRID_N - 1);
            iy = min(max(iy, 0), GRID_N - 1);
            iz = min(max(iz, 0), GRID_N - 1);
            g[u][s] = __ldg(sdf + ((ix << 16) | (iy << 8) | iz));
        }
    }

    // ---- consume: radius re-read from smem (broadcast, conflict-free) ----
    const float* mw = reinterpret_cast<const float*>(s_model) + l * 36 + 3;
    const float wgt = __ldg(weight);

    #pragma unroll
    for (int u = 0; u < ILP; u++) {
        float m = mw[0] - g[u][0];
        #pragma unroll
        for (int s = 1; s < N_SPH; s++)
            m = fmaxf(m, mw[s * 4] - g[u][s]);

        // threshold + clip + /0.25 (== *4 exactly)
        float res = fminf(fmaxf(m - 0.01f, 0.0f), 0.5f) * 4.0f;

        // sum over 8 links (lanes l..l+7 share (b,h))
        res += __shfl_xor_sync(0xffffffffu, res, 1);
        res += __shfl_xor_sync(0xffffffffu, res, 2);
        res += __shfl_xor_sync(0xffffffffu, res, 4);

        if (l == 0)
            out[blockIdx.x * BH_PER_BLOCK + u * 16 + lbh] = wgt * res;
    }
}

extern "C" void kernel_launch(void* const* d_in, const int* in_sizes, int n_in,
                              void* d_out, int out_size) {
    const float* link_pos = (const float*)d_in[0];
    const float* link_rot = (const float*)d_in[1];
    const float* sph_ctr  = (const float*)d_in[2];
    const float* sph_rad  = (const float*)d_in[3];
    const float* sdf      = (const float*)d_in[4];
    const float* weight   = (const float*)d_in[5];
    float* out = (float*)d_out;

    const int n_bh   = out_size;               // B*H = 32768
    const int blocks = n_bh / BH_PER_BLOCK;    // 512 blocks of 128 threads

    vox_cost_kernel<<<blocks, 128>>>(link_pos, link_rot, sph_ctr, sph_rad,
                                     sdf, weight, out);
}